// round 10
// baseline (speedup 1.0000x reference)
#include <cuda_runtime.h>

// Problem shape (fixed by setup_inputs): BATCH=16384, P=16, D=2048
#define BATCH   16384
#define PNUM    16
#define DIM     2048
#define NGROUP  (BATCH / PNUM)     // 1024
#define D4      (DIM / 4)          // 512 float4 per row
#define THREADS 256
#define RB      8                  // rows per load batch (8 rows x 2 cols = 16 live loads)
#define NBLK    512                // CTAs
#define GPB     (NGROUP / NBLK)    // 2 groups per CTA

// Device-global scratch (statically zero-initialized; finalizing block resets
// it each run -> deterministic across graph replays, no init launch).
__device__ double        g_acc   = 0.0;
__device__ unsigned int  g_count = 0u;

// min 3 CTAs/SM -> ptxas register budget ~85: keeps 16 float4 loads in flight.
__global__ __launch_bounds__(THREADS, 3) void fl_fused_kernel(const float4* __restrict__ f,
                                                              float* __restrict__ out) {
    const int c0 = threadIdx.x;
    const int c1 = threadIdx.x + THREADS;

    double d = 0.0;  // per-thread contribution to sum_g (B_g - A_g)

    #pragma unroll
    for (int gi = 0; gi < GPB; gi++) {
        const int g = blockIdx.x + gi * NBLK;
        const float4* base = f + (size_t)g * PNUM * D4;

        float  ssq0 = 0.0f, ssq1 = 0.0f;
        float4 cs0 = make_float4(0.f, 0.f, 0.f, 0.f);
        float4 cs1 = make_float4(0.f, 0.f, 0.f, 0.f);

        #pragma unroll
        for (int rb = 0; rb < PNUM; rb += RB) {
            // 16 independent 128-bit loads, all live before any FMA consumes them.
            float4 v[RB], w[RB];
            #pragma unroll
            for (int i = 0; i < RB; i++) v[i] = base[(rb + i) * D4 + c0];
            #pragma unroll
            for (int i = 0; i < RB; i++) w[i] = base[(rb + i) * D4 + c1];

            #pragma unroll
            for (int i = 0; i < RB; i++) {
                cs0.x += v[i].x; cs0.y += v[i].y; cs0.z += v[i].z; cs0.w += v[i].w;
                ssq0  += v[i].x * v[i].x + v[i].y * v[i].y + v[i].z * v[i].z + v[i].w * v[i].w;
            }
            #pragma unroll
            for (int i = 0; i < RB; i++) {
                cs1.x += w[i].x; cs1.y += w[i].y; cs1.z += w[i].z; cs1.w += w[i].w;
                ssq1  += w[i].x * w[i].x + w[i].y * w[i].y + w[i].z * w[i].z + w[i].w * w[i].w;
            }
        }

        float scol = cs0.x * cs0.x + cs0.y * cs0.y + cs0.z * cs0.z + cs0.w * cs0.w
                   + cs1.x * cs1.x + cs1.y * cs1.y + cs1.z * cs1.z + cs1.w * cs1.w;

        d += (double)((ssq0 + ssq1) - scol);
    }

    // warp reduce
    #pragma unroll
    for (int o = 16; o; o >>= 1)
        d += __shfl_xor_sync(0xffffffffu, d, o);

    __shared__ double sh[THREADS / 32];
    if ((threadIdx.x & 31) == 0) sh[threadIdx.x >> 5] = d;
    __syncthreads();

    if (threadIdx.x == 0) {
        double b = 0.0;
        #pragma unroll
        for (int w2 = 0; w2 < THREADS / 32; w2++) b += sh[w2];
        atomicAdd(&g_acc, b);
        __threadfence();
        unsigned int ticket = atomicAdd(&g_count, 1u);
        if (ticket == NBLK - 1u) {
            const double pairs = (double)PNUM * (PNUM - 1) / 2.0;  // 120
            double acc = g_acc;                                     // all adds visible
            out[0] = (float)(1.0 + acc / (2.0 * pairs * (double)NGROUP));
            // reset for next invocation / graph replay
            g_acc   = 0.0;
            g_count = 0u;
        }
    }
}

extern "C" void kernel_launch(void* const* d_in, const int* in_sizes, int n_in,
                              void* d_out, int out_size) {
    (void)in_sizes; (void)n_in; (void)out_size;
    const float4* f = (const float4*)d_in[0];
    float* out = (float*)d_out;
    fl_fused_kernel<<<NBLK, THREADS>>>(f, out);
}

// round 11
// speedup vs baseline: 1.0389x; 1.0389x over previous
#include <cuda_runtime.h>

// Problem shape (fixed by setup_inputs): BATCH=16384, P=16, D=2048
#define BATCH   16384
#define PNUM    16
#define DIM     2048
#define NGROUP  (BATCH / PNUM)     // 1024
#define D4      (DIM / 4)          // 512 float4 per row
#define THREADS 256
#define RB      8                  // rows per load batch (8 rows x 2 cols = 16 live loads)
#define NACC    8                  // accumulator buckets (spread across L2 slices)

// Bucketed accumulators, 256B apart to land on distinct L2 slices (avoid the
// bit-7 hash pairing). Statically zero-initialized; the finalizing block resets
// everything each run -> deterministic across graph replays, no init launch.
struct __align__(256) PadAcc { double v; char pad[248]; };
__device__ PadAcc        g_acc[NACC];   // zero-initialized
__device__ unsigned int  g_count = 0u;

// min 3 CTAs/SM -> ptxas register budget ~85: keeps 16 float4 loads in flight.
__global__ __launch_bounds__(THREADS, 3) void fl_fused_kernel(const float4* __restrict__ f,
                                                              float* __restrict__ out) {
    const int g = blockIdx.x;
    const float4* base = f + (size_t)g * PNUM * D4;

    const int c0 = threadIdx.x;
    const int c1 = threadIdx.x + THREADS;

    float  ssq0 = 0.0f, ssq1 = 0.0f;
    float4 cs0 = make_float4(0.f, 0.f, 0.f, 0.f);
    float4 cs1 = make_float4(0.f, 0.f, 0.f, 0.f);

    #pragma unroll
    for (int rb = 0; rb < PNUM; rb += RB) {
        // 16 independent 128-bit loads, all live before any FMA consumes them.
        float4 v[RB], w[RB];
        #pragma unroll
        for (int i = 0; i < RB; i++) v[i] = base[(rb + i) * D4 + c0];
        #pragma unroll
        for (int i = 0; i < RB; i++) w[i] = base[(rb + i) * D4 + c1];

        #pragma unroll
        for (int i = 0; i < RB; i++) {
            cs0.x += v[i].x; cs0.y += v[i].y; cs0.z += v[i].z; cs0.w += v[i].w;
            ssq0  += v[i].x * v[i].x + v[i].y * v[i].y + v[i].z * v[i].z + v[i].w * v[i].w;
        }
        #pragma unroll
        for (int i = 0; i < RB; i++) {
            cs1.x += w[i].x; cs1.y += w[i].y; cs1.z += w[i].z; cs1.w += w[i].w;
            ssq1  += w[i].x * w[i].x + w[i].y * w[i].y + w[i].z * w[i].z + w[i].w * w[i].w;
        }
    }

    float scol = cs0.x * cs0.x + cs0.y * cs0.y + cs0.z * cs0.z + cs0.w * cs0.w
               + cs1.x * cs1.x + cs1.y * cs1.y + cs1.z * cs1.z + cs1.w * cs1.w;

    double d = (double)((ssq0 + ssq1) - scol);

    // warp reduce
    #pragma unroll
    for (int o = 16; o; o >>= 1)
        d += __shfl_xor_sync(0xffffffffu, d, o);

    __shared__ double sh[THREADS / 32];
    if ((threadIdx.x & 31) == 0) sh[threadIdx.x >> 5] = d;
    __syncthreads();

    if (threadIdx.x == 0) {
        double b = 0.0;
        #pragma unroll
        for (int w2 = 0; w2 < THREADS / 32; w2++) b += sh[w2];
        atomicAdd(&g_acc[g & (NACC - 1)].v, b);
        __threadfence();
        unsigned int ticket = atomicAdd(&g_count, 1u);
        if (ticket == NGROUP - 1u) {
            double acc = 0.0;
            #pragma unroll
            for (int i = 0; i < NACC; i++) acc += g_acc[i].v;   // all adds visible
            const double pairs = (double)PNUM * (PNUM - 1) / 2.0;  // 120
            out[0] = (float)(1.0 + acc / (2.0 * pairs * (double)NGROUP));
            // reset for next invocation / graph replay
            #pragma unroll
            for (int i = 0; i < NACC; i++) g_acc[i].v = 0.0;
            g_count = 0u;
        }
    }
}

extern "C" void kernel_launch(void* const* d_in, const int* in_sizes, int n_in,
                              void* d_out, int out_size) {
    (void)in_sizes; (void)n_in; (void)out_size;
    const float4* f = (const float4*)d_in[0];
    float* out = (float*)d_out;
    fl_fused_kernel<<<NGROUP, THREADS>>>(f, out);
}

// round 12
// speedup vs baseline: 1.0538x; 1.0144x over previous
#include <cuda_runtime.h>

// Problem shape (fixed by setup_inputs): BATCH=16384, P=16, D=2048
#define BATCH   16384
#define PNUM    16
#define DIM     2048
#define NGROUP  (BATCH / PNUM)     // 1024
#define D4      (DIM / 4)          // 512 float4 per row
#define THREADS 256
#define RB      8                  // rows per load batch (8 rows x 2 cols = 16 live loads)

// Device-global scratch (statically zero-initialized; finalizing block resets
// it each run -> deterministic across graph replays, no init launch).
__device__ double        g_acc   = 0.0;
__device__ unsigned int  g_count = 0u;

// min 3 CTAs/SM -> ptxas register budget ~85: keeps 16 float4 loads in flight.
__global__ __launch_bounds__(THREADS, 3) void fl_fused_kernel(const float4* __restrict__ f,
                                                              float* __restrict__ out) {
    const int g = blockIdx.x;
    const float4* base = f + (size_t)g * PNUM * D4;

    const int c0 = threadIdx.x;
    const int c1 = threadIdx.x + THREADS;

    float  ssq0 = 0.0f, ssq1 = 0.0f;
    float4 cs0 = make_float4(0.f, 0.f, 0.f, 0.f);
    float4 cs1 = make_float4(0.f, 0.f, 0.f, 0.f);

    #pragma unroll
    for (int rb = 0; rb < PNUM; rb += RB) {
        // 16 independent 128-bit loads, all live before any FMA consumes them.
        float4 v[RB], w[RB];
        #pragma unroll
        for (int i = 0; i < RB; i++) v[i] = base[(rb + i) * D4 + c0];
        #pragma unroll
        for (int i = 0; i < RB; i++) w[i] = base[(rb + i) * D4 + c1];

        #pragma unroll
        for (int i = 0; i < RB; i++) {
            cs0.x += v[i].x; cs0.y += v[i].y; cs0.z += v[i].z; cs0.w += v[i].w;
            ssq0  += v[i].x * v[i].x + v[i].y * v[i].y + v[i].z * v[i].z + v[i].w * v[i].w;
        }
        #pragma unroll
        for (int i = 0; i < RB; i++) {
            cs1.x += w[i].x; cs1.y += w[i].y; cs1.z += w[i].z; cs1.w += w[i].w;
            ssq1  += w[i].x * w[i].x + w[i].y * w[i].y + w[i].z * w[i].z + w[i].w * w[i].w;
        }
    }

    float scol = cs0.x * cs0.x + cs0.y * cs0.y + cs0.z * cs0.z + cs0.w * cs0.w
               + cs1.x * cs1.x + cs1.y * cs1.y + cs1.z * cs1.z + cs1.w * cs1.w;

    double d = (double)((ssq0 + ssq1) - scol);

    // warp reduce
    #pragma unroll
    for (int o = 16; o; o >>= 1)
        d += __shfl_xor_sync(0xffffffffu, d, o);

    __shared__ double sh[THREADS / 32];
    if ((threadIdx.x & 31) == 0) sh[threadIdx.x >> 5] = d;
    __syncthreads();

    if (threadIdx.x == 0) {
        double b = 0.0;
        #pragma unroll
        for (int w2 = 0; w2 < THREADS / 32; w2++) b += sh[w2];
        atomicAdd(&g_acc, b);
        __threadfence();
        unsigned int ticket = atomicAdd(&g_count, 1u);
        if (ticket == NGROUP - 1u) {
            const double pairs = (double)PNUM * (PNUM - 1) / 2.0;  // 120
            double acc = g_acc;                                     // all adds visible
            out[0] = (float)(1.0 + acc / (2.0 * pairs * (double)NGROUP));
            // reset for next invocation / graph replay
            g_acc   = 0.0;
            g_count = 0u;
        }
    }
}

extern "C" void kernel_launch(void* const* d_in, const int* in_sizes, int n_in,
                              void* d_out, int out_size) {
    (void)in_sizes; (void)n_in; (void)out_size;
    const float4* f = (const float4*)d_in[0];
    float* out = (float*)d_out;
    fl_fused_kernel<<<NGROUP, THREADS>>>(f, out);
}